// round 3
// baseline (speedup 1.0000x reference)
#include <cuda_runtime.h>
#include <cuda_bf16.h>
#include <cstdint>

// ============================================================================
// Int8Linear: out[M,N] = x[M,K] @ (q[N,K]*scale)^T + bias
//   M = 16384, K = 4096, N = 4096, fp32 in/out.
// Harness compiles for plain sm_100 (no 'a' suffix) -> tcgen05/TMEM are NOT
// available. Use baseline-PTX path: cp.async + ldmatrix + mma.sync (bf16).
// Precision: x split into bf16 hi+lo, weights exact in bf16, both halves
// accumulated into the SAME fp32 accumulators (effective ~16 mantissa bits).
// ============================================================================

static constexpr int M_DIM = 16384;
static constexpr int N_DIM = 4096;
static constexpr int K_DIM = 4096;

static constexpr int BM = 128;
static constexpr int BN = 128;
static constexpr int BK = 32;
static constexpr int STAGES = 4;
static constexpr int THREADS = 256;
static constexpr int NKT = K_DIM / BK;                 // 128 k-tiles

static constexpr int TILE_BYTES = BM * BK * 2;         // 8192 (A_hi, A_lo, B each)
static constexpr int STAGE_BYTES = 3 * TILE_BYTES;     // 24576
static constexpr int SMEM_TOTAL = STAGES * STAGE_BYTES;// 98304
static constexpr int OFF_ALO = TILE_BYTES;             // +8192
static constexpr int OFF_B   = 2 * TILE_BYTES;         // +16384

// ---------------- scratch (device globals: allocation-free) ----------------
__device__ __align__(1024) __nv_bfloat16 g_wb [(size_t)N_DIM * K_DIM];   // 32 MB
__device__ __align__(1024) __nv_bfloat16 g_xhi[(size_t)M_DIM * K_DIM];   // 128 MB
__device__ __align__(1024) __nv_bfloat16 g_xlo[(size_t)M_DIM * K_DIM];   // 128 MB

// ---------------- PTX helpers (all baseline sm_80/sm_90 PTX) ----------------
__device__ __forceinline__ uint32_t smem_to_u32(const void* p) {
    uint32_t a;
    asm("{ .reg .u64 t; cvta.to.shared.u64 t, %1; cvt.u32.u64 %0, t; }"
        : "=r"(a) : "l"(p));
    return a;
}

__device__ __forceinline__ void cp16(uint32_t s, const void* g) {
    asm volatile("cp.async.cg.shared.global [%0], [%1], 16;"
                 :: "r"(s), "l"(g) : "memory");
}
__device__ __forceinline__ void cp_commit() {
    asm volatile("cp.async.commit_group;" ::: "memory");
}

__device__ __forceinline__ void ldm_x4(uint32_t* r, uint32_t addr) {
    asm volatile("ldmatrix.sync.aligned.m8n8.x4.shared.b16 {%0,%1,%2,%3}, [%4];"
                 : "=r"(r[0]), "=r"(r[1]), "=r"(r[2]), "=r"(r[3]) : "r"(addr));
}
__device__ __forceinline__ void ldm_x2(uint32_t* r, uint32_t addr) {
    asm volatile("ldmatrix.sync.aligned.m8n8.x2.shared.b16 {%0,%1}, [%2];"
                 : "=r"(r[0]), "=r"(r[1]) : "r"(addr));
}

__device__ __forceinline__ void mma_bf16(float* d, const uint32_t* a,
                                         const uint32_t* b) {
    asm volatile(
        "mma.sync.aligned.m16n8k16.row.col.f32.bf16.bf16.f32 "
        "{%0,%1,%2,%3}, {%4,%5,%6,%7}, {%8,%9}, {%0,%1,%2,%3};"
        : "+f"(d[0]), "+f"(d[1]), "+f"(d[2]), "+f"(d[3])
        : "r"(a[0]), "r"(a[1]), "r"(a[2]), "r"(a[3]), "r"(b[0]), "r"(b[1]));
}

// ---------------- preprocessing kernels ----------------
__global__ void wconv_kernel(const int* __restrict__ q) {
    const int n4 = N_DIM * K_DIM / 4;
    for (int i = blockIdx.x * blockDim.x + threadIdx.x; i < n4;
         i += gridDim.x * blockDim.x) {
        int4 v = reinterpret_cast<const int4*>(q)[i];
        __nv_bfloat162 a = __floats2bfloat162_rn((float)v.x, (float)v.y);
        __nv_bfloat162 b = __floats2bfloat162_rn((float)v.z, (float)v.w);
        uint2 o;
        o.x = *reinterpret_cast<uint32_t*>(&a);
        o.y = *reinterpret_cast<uint32_t*>(&b);
        reinterpret_cast<uint2*>(g_wb)[i] = o;
    }
}

__global__ void xsplit_kernel(const float* __restrict__ x) {
    const int n4 = M_DIM * K_DIM / 4;
    for (int i = blockIdx.x * blockDim.x + threadIdx.x; i < n4;
         i += gridDim.x * blockDim.x) {
        float4 v = reinterpret_cast<const float4*>(x)[i];
        __nv_bfloat16 hx = __float2bfloat16_rn(v.x);
        __nv_bfloat16 hy = __float2bfloat16_rn(v.y);
        __nv_bfloat16 hz = __float2bfloat16_rn(v.z);
        __nv_bfloat16 hw = __float2bfloat16_rn(v.w);
        float lx = v.x - __bfloat162float(hx);
        float ly = v.y - __bfloat162float(hy);
        float lz = v.z - __bfloat162float(hz);
        float lw = v.w - __bfloat162float(hw);
        __nv_bfloat162 h0; h0.x = hx; h0.y = hy;
        __nv_bfloat162 h1; h1.x = hz; h1.y = hw;
        __nv_bfloat162 l0 = __floats2bfloat162_rn(lx, ly);
        __nv_bfloat162 l1 = __floats2bfloat162_rn(lz, lw);
        uint2 oh, ol;
        oh.x = *reinterpret_cast<uint32_t*>(&h0);
        oh.y = *reinterpret_cast<uint32_t*>(&h1);
        ol.x = *reinterpret_cast<uint32_t*>(&l0);
        ol.y = *reinterpret_cast<uint32_t*>(&l1);
        reinterpret_cast<uint2*>(g_xhi)[i] = oh;
        reinterpret_cast<uint2*>(g_xlo)[i] = ol;
    }
}

// ---------------- GEMM kernel ----------------
// smem tile layout (per stage): A_hi[128][32] | A_lo[128][32] | B[128][32],
// each row = 64B = 4 chunks of 16B, physical chunk = c ^ ((row>>1)&3).
__global__ __launch_bounds__(THREADS, 2) void gemm_kernel(
    const float* __restrict__ scale_p,
    const float* __restrict__ bias,
    float* __restrict__ out) {
    extern __shared__ char smem[];
    uint32_t sb = smem_to_u32(smem);
    const int tid = threadIdx.x;
    const int lane = tid & 31, wid = tid >> 5;
    const int wm = wid >> 2;          // 0..1 -> 64-row slice
    const int wn = wid & 3;           // 0..3 -> 32-col slice

    const int m_tile = (int)blockIdx.x >> 5;   // 0..127
    const int n_tile = (int)blockIdx.x & 31;   // 0..31
    const int m0 = m_tile * BM;
    const int n0 = n_tile * BN;

    // ---- cp.async per-thread assignment: 2 chunks per tile, 3 tiles ----
    const int r1 = tid >> 2,          c1 = tid & 3;
    const int r2 = (tid + 256) >> 2,  c2 = (tid + 256) & 3;
    const uint32_t so1 = (uint32_t)(r1 * 64 + ((c1 ^ ((r1 >> 1) & 3)) << 4));
    const uint32_t so2 = (uint32_t)(r2 * 64 + ((c2 ^ ((r2 >> 1) & 3)) << 4));
    const __nv_bfloat16* ghi1 = g_xhi + (size_t)(m0 + r1) * K_DIM + c1 * 8;
    const __nv_bfloat16* ghi2 = g_xhi + (size_t)(m0 + r2) * K_DIM + c2 * 8;
    const __nv_bfloat16* glo1 = g_xlo + (size_t)(m0 + r1) * K_DIM + c1 * 8;
    const __nv_bfloat16* glo2 = g_xlo + (size_t)(m0 + r2) * K_DIM + c2 * 8;
    const __nv_bfloat16* gb1  = g_wb  + (size_t)(n0 + r1) * K_DIM + c1 * 8;
    const __nv_bfloat16* gb2  = g_wb  + (size_t)(n0 + r2) * K_DIM + c2 * 8;

    // ---- ldmatrix per-lane address components ----
    const int rowA = wm * 64 + (lane & 7) + ((lane >> 3) & 1) * 8;  // + mi*16
    const int cbA  = (lane >> 4) & 1;
    const int swA  = (rowA >> 1) & 3;   // invariant under +mi*16
    const int lb   = lane & 15;
    const int rowB = wn * 32 + (lb & 7);                             // + ni*8
    const int cbB  = (lb >> 3) & 1;
    const int swB  = (rowB >> 1) & 3;   // invariant under +ni*8

    // ---- prologue: prefetch STAGES-1 k-tiles ----
    #pragma unroll
    for (int kt = 0; kt < STAGES - 1; kt++) {
        uint32_t st = sb + kt * STAGE_BYTES;
        int ko = kt * BK;
        cp16(st + so1,           ghi1 + ko);
        cp16(st + so2,           ghi2 + ko);
        cp16(st + OFF_ALO + so1, glo1 + ko);
        cp16(st + OFF_ALO + so2, glo2 + ko);
        cp16(st + OFF_B + so1,   gb1 + ko);
        cp16(st + OFF_B + so2,   gb2 + ko);
        cp_commit();
    }

    float acc[4][4][4];
    #pragma unroll
    for (int i = 0; i < 4; i++)
        #pragma unroll
        for (int j = 0; j < 4; j++)
            #pragma unroll
            for (int l = 0; l < 4; l++) acc[i][j][l] = 0.f;

    // ---- main loop ----
    for (int kt = 0; kt < NKT; kt++) {
        asm volatile("cp.async.wait_group 2;" ::: "memory");
        __syncthreads();

        int kn = kt + STAGES - 1;
        if (kn < NKT) {
            uint32_t st = sb + (kn & 3) * STAGE_BYTES;
            int ko = kn * BK;
            cp16(st + so1,           ghi1 + ko);
            cp16(st + so2,           ghi2 + ko);
            cp16(st + OFF_ALO + so1, glo1 + ko);
            cp16(st + OFF_ALO + so2, glo2 + ko);
            cp16(st + OFF_B + so1,   gb1 + ko);
            cp16(st + OFF_B + so2,   gb2 + ko);
        }
        cp_commit();

        uint32_t st = sb + (kt & 3) * STAGE_BYTES;
        #pragma unroll
        for (int s = 0; s < 2; s++) {
            uint32_t bfr[4][2];
            #pragma unroll
            for (int ni = 0; ni < 4; ni++) {
                uint32_t addr = st + OFF_B + (uint32_t)((rowB + ni * 8) * 64) +
                                (uint32_t)(((((s << 1) | cbB) ^ swB)) << 4);
                ldm_x2(bfr[ni], addr);
            }
            #pragma unroll
            for (int half = 0; half < 2; half++) {
                uint32_t abase = st + half * OFF_ALO;
                uint32_t afr[4][4];
                #pragma unroll
                for (int mi = 0; mi < 4; mi++) {
                    uint32_t addr = abase + (uint32_t)((rowA + mi * 16) * 64) +
                                    (uint32_t)(((((s << 1) | cbA) ^ swA)) << 4);
                    ldm_x4(afr[mi], addr);
                }
                #pragma unroll
                for (int mi = 0; mi < 4; mi++)
                    #pragma unroll
                    for (int ni = 0; ni < 4; ni++)
                        mma_bf16(acc[mi][ni], afr[mi], bfr[ni]);
            }
        }
    }

    // ---- epilogue: acc * scale + bias ----
    const float sc = __ldg(scale_p);
    #pragma unroll
    for (int mi = 0; mi < 4; mi++) {
        int r0 = m0 + wm * 64 + mi * 16 + (lane >> 2);
        float* o0 = out + (size_t)r0 * N_DIM;
        float* o1 = o0 + (size_t)8 * N_DIM;
        #pragma unroll
        for (int ni = 0; ni < 4; ni++) {
            int c = n0 + wn * 32 + ni * 8 + (lane & 3) * 2;
            float b0 = __ldg(bias + c), b1 = __ldg(bias + c + 1);
            float2 v0, v1;
            v0.x = acc[mi][ni][0] * sc + b0;
            v0.y = acc[mi][ni][1] * sc + b1;
            v1.x = acc[mi][ni][2] * sc + b0;
            v1.y = acc[mi][ni][3] * sc + b1;
            *reinterpret_cast<float2*>(o0 + c) = v0;
            *reinterpret_cast<float2*>(o1 + c) = v1;
        }
    }
}

// ---------------- host launch ----------------
extern "C" void kernel_launch(void* const* d_in, const int* in_sizes, int n_in,
                              void* d_out, int out_size) {
    const float* x     = (const float*)d_in[0];
    const int*   q     = (const int*)d_in[1];
    const float* scale = (const float*)d_in[2];
    const float* bias  = (const float*)d_in[3];
    float* out = (float*)d_out;

    wconv_kernel<<<1480, 256>>>(q);
    xsplit_kernel<<<2960, 256>>>(x);

    cudaFuncSetAttribute(gemm_kernel,
                         cudaFuncAttributeMaxDynamicSharedMemorySize, SMEM_TOTAL);
    dim3 grid((M_DIM / BM) * (N_DIM / BN));   // 128 * 32 = 4096
    gemm_kernel<<<grid, THREADS, SMEM_TOTAL>>>(scale, bias, out);
}

// round 4
// speedup vs baseline: 1.5667x; 1.5667x over previous
#include <cuda_runtime.h>
#include <cuda_bf16.h>
#include <cstdint>

// ============================================================================
// Int8Linear: out[M,N] = x[M,K] @ (q[N,K]*scale)^T + bias
//   M = 16384, K = 4096, N = 4096, fp32 in/out. Target: plain sm_100 PTX.
// Strategy: per-row two-level int8 quantization of x:
//   x ~= x_hi * s1 + x_lo * (s1/254),  s1 = rowmax/126
// Weights already int8. Both passes accumulate EXACTLY in s32 via
// mma.sync.m16n8k32.s8 (2x MAC rate of bf16 HMMA). Epilogue:
//   out = scale*s1[m]*(hi + lo/254) + bias.
// ============================================================================

static constexpr int M_DIM = 16384;
static constexpr int N_DIM = 4096;
static constexpr int K_DIM = 4096;

static constexpr int BM = 128;
static constexpr int BN = 128;
static constexpr int BK = 64;                          // 64 int8 k per stage
static constexpr int STAGES = 6;
static constexpr int THREADS = 256;
static constexpr int NKT = K_DIM / BK;                 // 64 k-tiles

static constexpr int TILE_BYTES = BM * BK;             // 8192 (A_hi, A_lo, B each)
static constexpr int STAGE_BYTES = 3 * TILE_BYTES;     // 24576
static constexpr int SMEM_TOTAL = STAGES * STAGE_BYTES;// 147456
static constexpr int OFF_ALO = TILE_BYTES;
static constexpr int OFF_B   = 2 * TILE_BYTES;

// ---------------- scratch (device globals: allocation-free) ----------------
__device__ __align__(1024) int8_t g_wq [(size_t)N_DIM * K_DIM];   // 16 MB
__device__ __align__(1024) int8_t g_xh8[(size_t)M_DIM * K_DIM];   // 64 MB
__device__ __align__(1024) int8_t g_xl8[(size_t)M_DIM * K_DIM];   // 64 MB
__device__ float g_s1[M_DIM];

// ---------------- PTX helpers (baseline sm_80/sm_90 PTX only) ----------------
__device__ __forceinline__ uint32_t smem_to_u32(const void* p) {
    uint32_t a;
    asm("{ .reg .u64 t; cvta.to.shared.u64 t, %1; cvt.u32.u64 %0, t; }"
        : "=r"(a) : "l"(p));
    return a;
}

__device__ __forceinline__ void cp16(uint32_t s, const void* g) {
    asm volatile("cp.async.cg.shared.global [%0], [%1], 16;"
                 :: "r"(s), "l"(g) : "memory");
}
__device__ __forceinline__ void cp_commit() {
    asm volatile("cp.async.commit_group;" ::: "memory");
}

__device__ __forceinline__ void ldm_x4(uint32_t* r, uint32_t addr) {
    asm volatile("ldmatrix.sync.aligned.m8n8.x4.shared.b16 {%0,%1,%2,%3}, [%4];"
                 : "=r"(r[0]), "=r"(r[1]), "=r"(r[2]), "=r"(r[3]) : "r"(addr));
}
__device__ __forceinline__ void ldm_x2(uint32_t* r, uint32_t addr) {
    asm volatile("ldmatrix.sync.aligned.m8n8.x2.shared.b16 {%0,%1}, [%2];"
                 : "=r"(r[0]), "=r"(r[1]) : "r"(addr));
}

__device__ __forceinline__ void mma_s8(int* d, const uint32_t* a,
                                       const uint32_t* b) {
    asm volatile(
        "mma.sync.aligned.m16n8k32.row.col.s32.s8.s8.s32 "
        "{%0,%1,%2,%3}, {%4,%5,%6,%7}, {%8,%9}, {%0,%1,%2,%3};"
        : "+r"(d[0]), "+r"(d[1]), "+r"(d[2]), "+r"(d[3])
        : "r"(a[0]), "r"(a[1]), "r"(a[2]), "r"(a[3]), "r"(b[0]), "r"(b[1]));
}

// ---------------- preprocessing ----------------
// Pack int32-stored int8 weights -> int8.
__global__ void wpack_kernel(const int* __restrict__ q) {
    const int n4 = N_DIM * K_DIM / 4;
    for (int i = blockIdx.x * blockDim.x + threadIdx.x; i < n4;
         i += gridDim.x * blockDim.x) {
        int4 v = reinterpret_cast<const int4*>(q)[i];
        uint32_t p = (uint32_t)(v.x & 0xff) | ((uint32_t)(v.y & 0xff) << 8) |
                     ((uint32_t)(v.z & 0xff) << 16) | ((uint32_t)(v.w & 0xff) << 24);
        reinterpret_cast<uint32_t*>(g_wq)[i] = p;
    }
}

// Per-row two-level int8 quantization of x. One block (256 thr) per row.
__global__ __launch_bounds__(256) void xquant_kernel(const float* __restrict__ x) {
    const int row = blockIdx.x;
    const int tid = threadIdx.x;
    const float4* xr = reinterpret_cast<const float4*>(x + (size_t)row * K_DIM);
    __shared__ float red[8];

    float m = 0.f;
    float4 v[4];
    #pragma unroll
    for (int i = 0; i < 4; i++) {
        v[i] = xr[tid + i * 256];
        m = fmaxf(m, fmaxf(fmaxf(fabsf(v[i].x), fabsf(v[i].y)),
                           fmaxf(fabsf(v[i].z), fabsf(v[i].w))));
    }
    #pragma unroll
    for (int o = 16; o > 0; o >>= 1)
        m = fmaxf(m, __shfl_xor_sync(0xffffffffu, m, o));
    if ((tid & 31) == 0) red[tid >> 5] = m;
    __syncthreads();
    if (tid < 8) {
        float t = red[tid];
        #pragma unroll
        for (int o = 4; o > 0; o >>= 1)
            t = fmaxf(t, __shfl_xor_sync(0xffu, t, o));
        if (tid == 0) red[0] = t;
    }
    __syncthreads();
    m = red[0];

    const float s1   = (m > 0.f) ? (m / 126.f) : 0.f;
    const float inv1 = (m > 0.f) ? (126.f / m) : 0.f;
    const float inv2 = inv1 * 254.f;

    int* oh = reinterpret_cast<int*>(g_xh8) + (size_t)row * (K_DIM / 4);
    int* ol = reinterpret_cast<int*>(g_xl8) + (size_t)row * (K_DIM / 4);
    #pragma unroll
    for (int i = 0; i < 4; i++) {
        float4 w = v[i];
        int h0 = __float2int_rn(w.x * inv1);
        int h1 = __float2int_rn(w.y * inv1);
        int h2 = __float2int_rn(w.z * inv1);
        int h3 = __float2int_rn(w.w * inv1);
        int l0 = __float2int_rn((w.x - (float)h0 * s1) * inv2);
        int l1 = __float2int_rn((w.y - (float)h1 * s1) * inv2);
        int l2 = __float2int_rn((w.z - (float)h2 * s1) * inv2);
        int l3 = __float2int_rn((w.w - (float)h3 * s1) * inv2);
        uint32_t ph = (uint32_t)(h0 & 0xff) | ((uint32_t)(h1 & 0xff) << 8) |
                      ((uint32_t)(h2 & 0xff) << 16) | ((uint32_t)(h3 & 0xff) << 24);
        uint32_t pl = (uint32_t)(l0 & 0xff) | ((uint32_t)(l1 & 0xff) << 8) |
                      ((uint32_t)(l2 & 0xff) << 16) | ((uint32_t)(l3 & 0xff) << 24);
        oh[tid + i * 256] = (int)ph;
        ol[tid + i * 256] = (int)pl;
    }
    if (tid == 0) g_s1[row] = s1;
}

// ---------------- GEMM kernel ----------------
// Per-stage smem: A_hi[128][64B] | A_lo[128][64B] | B[128][64B].
// Row = 64B = 4 chunks of 16B; physical chunk = c ^ ((row>>1)&3).
__global__ __launch_bounds__(THREADS, 1) void gemm_kernel(
    const float* __restrict__ scale_p,
    const float* __restrict__ bias,
    float* __restrict__ out) {
    extern __shared__ char smem[];
    uint32_t sb = smem_to_u32(smem);
    const int tid = threadIdx.x;
    const int lane = tid & 31, wid = tid >> 5;
    const int wm = wid >> 2;          // 0..1 -> 64-row slice
    const int wn = wid & 3;           // 0..3 -> 32-col slice

    const int m_tile = (int)blockIdx.x >> 5;   // 0..127
    const int n_tile = (int)blockIdx.x & 31;   // 0..31
    const int m0 = m_tile * BM;
    const int n0 = n_tile * BN;

    // cp.async assignment: 512 chunks of 16B per tile, 2 per thread, 3 tiles
    const int r1 = tid >> 2,          c1 = tid & 3;
    const int r2 = (tid + 256) >> 2,  c2 = (tid + 256) & 3;
    const uint32_t so1 = (uint32_t)(r1 * 64 + ((c1 ^ ((r1 >> 1) & 3)) << 4));
    const uint32_t so2 = (uint32_t)(r2 * 64 + ((c2 ^ ((r2 >> 1) & 3)) << 4));
    const int8_t* ghi1 = g_xh8 + (size_t)(m0 + r1) * K_DIM + c1 * 16;
    const int8_t* ghi2 = g_xh8 + (size_t)(m0 + r2) * K_DIM + c2 * 16;
    const int8_t* glo1 = g_xl8 + (size_t)(m0 + r1) * K_DIM + c1 * 16;
    const int8_t* glo2 = g_xl8 + (size_t)(m0 + r2) * K_DIM + c2 * 16;
    const int8_t* gb1  = g_wq  + (size_t)(n0 + r1) * K_DIM + c1 * 16;
    const int8_t* gb2  = g_wq  + (size_t)(n0 + r2) * K_DIM + c2 * 16;

    // ldmatrix lane address components (16B chunk = 16 k int8)
    const int rowA = wm * 64 + (lane & 7) + ((lane >> 3) & 1) * 8;  // + mi*16
    const int cbA  = (lane >> 4) & 1;
    const int swA  = (rowA >> 1) & 3;
    const int lb   = lane & 15;
    const int rowB = wn * 32 + (lb & 7);                             // + ni*8
    const int cbB  = (lb >> 3) & 1;
    const int swB  = (rowB >> 1) & 3;

    // prologue
    #pragma unroll
    for (int kt = 0; kt < STAGES - 1; kt++) {
        uint32_t st = sb + kt * STAGE_BYTES;
        int ko = kt * BK;
        cp16(st + so1,           ghi1 + ko);
        cp16(st + so2,           ghi2 + ko);
        cp16(st + OFF_ALO + so1, glo1 + ko);
        cp16(st + OFF_ALO + so2, glo2 + ko);
        cp16(st + OFF_B + so1,   gb1 + ko);
        cp16(st + OFF_B + so2,   gb2 + ko);
        cp_commit();
    }

    int acch[4][4][4];
    int accl[4][4][4];
    #pragma unroll
    for (int i = 0; i < 4; i++)
        #pragma unroll
        for (int j = 0; j < 4; j++)
            #pragma unroll
            for (int l = 0; l < 4; l++) { acch[i][j][l] = 0; accl[i][j][l] = 0; }

    // main loop
    for (int kt = 0; kt < NKT; kt++) {
        asm volatile("cp.async.wait_group %0;" :: "n"(STAGES - 2) : "memory");
        __syncthreads();

        int kn = kt + STAGES - 1;
        if (kn < NKT) {
            uint32_t st = sb + (kn % STAGES) * STAGE_BYTES;
            int ko = kn * BK;
            cp16(st + so1,           ghi1 + ko);
            cp16(st + so2,           ghi2 + ko);
            cp16(st + OFF_ALO + so1, glo1 + ko);
            cp16(st + OFF_ALO + so2, glo2 + ko);
            cp16(st + OFF_B + so1,   gb1 + ko);
            cp16(st + OFF_B + so2,   gb2 + ko);
        }
        cp_commit();

        uint32_t st = sb + (kt % STAGES) * STAGE_BYTES;
        #pragma unroll
        for (int s = 0; s < 2; s++) {       // two k32 steps per stage
            uint32_t bfr[4][2];
            #pragma unroll
            for (int ni = 0; ni < 4; ni++) {
                uint32_t addr = st + OFF_B + (uint32_t)((rowB + ni * 8) * 64) +
                                (uint32_t)(((((s << 1) | cbB) ^ swB)) << 4);
                ldm_x2(bfr[ni], addr);
            }
            {   // hi half
                uint32_t afr[4][4];
                #pragma unroll
                for (int mi = 0; mi < 4; mi++) {
                    uint32_t addr = st + (uint32_t)((rowA + mi * 16) * 64) +
                                    (uint32_t)(((((s << 1) | cbA) ^ swA)) << 4);
                    ldm_x4(afr[mi], addr);
                }
                #pragma unroll
                for (int mi = 0; mi < 4; mi++)
                    #pragma unroll
                    for (int ni = 0; ni < 4; ni++)
                        mma_s8(acch[mi][ni], afr[mi], bfr[ni]);
            }
            {   // lo half
                uint32_t afr[4][4];
                #pragma unroll
                for (int mi = 0; mi < 4; mi++) {
                    uint32_t addr = st + OFF_ALO + (uint32_t)((rowA + mi * 16) * 64) +
                                    (uint32_t)(((((s << 1) | cbA) ^ swA)) << 4);
                    ldm_x4(afr[mi], addr);
                }
                #pragma unroll
                for (int mi = 0; mi < 4; mi++)
                    #pragma unroll
                    for (int ni = 0; ni < 4; ni++)
                        mma_s8(accl[mi][ni], afr[mi], bfr[ni]);
            }
        }
    }

    // epilogue: out = sc*s1[m]*(hi + lo/254) + bias
    const float sc = __ldg(scale_p);
    #pragma unroll
    for (int mi = 0; mi < 4; mi++) {
        int r0 = m0 + wm * 64 + mi * 16 + (lane >> 2);
        float f0  = sc * __ldg(g_s1 + r0);
        float f1  = sc * __ldg(g_s1 + r0 + 8);
        float f0l = f0 * (1.f / 254.f);
        float f1l = f1 * (1.f / 254.f);
        float* o0 = out + (size_t)r0 * N_DIM;
        float* o1 = o0 + (size_t)8 * N_DIM;
        #pragma unroll
        for (int ni = 0; ni < 4; ni++) {
            int c = n0 + wn * 32 + ni * 8 + (lane & 3) * 2;
            float b0 = __ldg(bias + c), b1 = __ldg(bias + c + 1);
            float2 v0, v1;
            v0.x = f0 * (float)acch[mi][ni][0] + f0l * (float)accl[mi][ni][0] + b0;
            v0.y = f0 * (float)acch[mi][ni][1] + f0l * (float)accl[mi][ni][1] + b1;
            v1.x = f1 * (float)acch[mi][ni][2] + f1l * (float)accl[mi][ni][2] + b0;
            v1.y = f1 * (float)acch[mi][ni][3] + f1l * (float)accl[mi][ni][3] + b1;
            *reinterpret_cast<float2*>(o0 + c) = v0;
            *reinterpret_cast<float2*>(o1 + c) = v1;
        }
    }
}

// ---------------- host launch ----------------
extern "C" void kernel_launch(void* const* d_in, const int* in_sizes, int n_in,
                              void* d_out, int out_size) {
    const float* x     = (const float*)d_in[0];
    const int*   q     = (const int*)d_in[1];
    const float* scale = (const float*)d_in[2];
    const float* bias  = (const float*)d_in[3];
    float* out = (float*)d_out;

    wpack_kernel<<<1480, 256>>>(q);
    xquant_kernel<<<M_DIM, 256>>>(x);

    cudaFuncSetAttribute(gemm_kernel,
                         cudaFuncAttributeMaxDynamicSharedMemorySize, SMEM_TOTAL);
    dim3 grid((M_DIM / BM) * (N_DIM / BN));   // 4096
    gemm_kernel<<<grid, THREADS, SMEM_TOTAL>>>(scale, bias, out);
}

// round 5
// speedup vs baseline: 2.0631x; 1.3168x over previous
#include <cuda_runtime.h>
#include <cuda_bf16.h>
#include <cstdint>

// ============================================================================
// Int8Linear: out[M,N] = x[M,K] @ (q[N,K]*scale)^T + bias
//   M = 16384, K = 4096, N = 4096, fp32 in/out. Target: plain sm_100 PTX.
// Two-level int8 quantization of x (per row): x ~= x_hi*s1 + x_lo*(s1/254).
// Both passes exact s32 via mma.sync.m16n8k32.s8.
// R5: software-pipelined fragments (ldmatrix overlapped with mma across the
// stage barrier) + 4m x 2n warp layout (warp tile 32x64) to cut smem reads.
// ============================================================================

static constexpr int M_DIM = 16384;
static constexpr int N_DIM = 4096;
static constexpr int K_DIM = 4096;

static constexpr int BM = 128;
static constexpr int BN = 128;
static constexpr int BK = 64;                          // int8 k per stage
static constexpr int STAGES = 6;
static constexpr int THREADS = 256;
static constexpr int NKT = K_DIM / BK;                 // 64 k-tiles

static constexpr int TILE_BYTES = BM * BK;             // 8192 (A_hi, A_lo, B each)
static constexpr int STAGE_BYTES = 3 * TILE_BYTES;     // 24576
static constexpr int SMEM_TOTAL = STAGES * STAGE_BYTES;// 147456
static constexpr int OFF_ALO = TILE_BYTES;
static constexpr int OFF_B   = 2 * TILE_BYTES;

// ---------------- scratch (device globals: allocation-free) ----------------
__device__ __align__(1024) int8_t g_wq [(size_t)N_DIM * K_DIM];   // 16 MB
__device__ __align__(1024) int8_t g_xh8[(size_t)M_DIM * K_DIM];   // 64 MB
__device__ __align__(1024) int8_t g_xl8[(size_t)M_DIM * K_DIM];   // 64 MB
__device__ float g_s1[M_DIM];

// ---------------- PTX helpers (baseline sm_80/sm_90 PTX only) ----------------
__device__ __forceinline__ uint32_t smem_to_u32(const void* p) {
    uint32_t a;
    asm("{ .reg .u64 t; cvta.to.shared.u64 t, %1; cvt.u32.u64 %0, t; }"
        : "=r"(a) : "l"(p));
    return a;
}

__device__ __forceinline__ void cp16(uint32_t s, const void* g) {
    asm volatile("cp.async.cg.shared.global [%0], [%1], 16;"
                 :: "r"(s), "l"(g) : "memory");
}
__device__ __forceinline__ void cp_commit() {
    asm volatile("cp.async.commit_group;" ::: "memory");
}

__device__ __forceinline__ void ldm_x4(uint32_t* r, uint32_t addr) {
    asm volatile("ldmatrix.sync.aligned.m8n8.x4.shared.b16 {%0,%1,%2,%3}, [%4];"
                 : "=r"(r[0]), "=r"(r[1]), "=r"(r[2]), "=r"(r[3]) : "r"(addr));
}

__device__ __forceinline__ void mma_s8(int* d, const uint32_t* a,
                                       const uint32_t* b) {
    asm volatile(
        "mma.sync.aligned.m16n8k32.row.col.s32.s8.s8.s32 "
        "{%0,%1,%2,%3}, {%4,%5,%6,%7}, {%8,%9}, {%0,%1,%2,%3};"
        : "+r"(d[0]), "+r"(d[1]), "+r"(d[2]), "+r"(d[3])
        : "r"(a[0]), "r"(a[1]), "r"(a[2]), "r"(a[3]), "r"(b[0]), "r"(b[1]));
}

// ---------------- preprocessing ----------------
__global__ void wpack_kernel(const int* __restrict__ q) {
    const int n4 = N_DIM * K_DIM / 4;
    for (int i = blockIdx.x * blockDim.x + threadIdx.x; i < n4;
         i += gridDim.x * blockDim.x) {
        int4 v = reinterpret_cast<const int4*>(q)[i];
        uint32_t p = (uint32_t)(v.x & 0xff) | ((uint32_t)(v.y & 0xff) << 8) |
                     ((uint32_t)(v.z & 0xff) << 16) | ((uint32_t)(v.w & 0xff) << 24);
        reinterpret_cast<uint32_t*>(g_wq)[i] = p;
    }
}

__global__ __launch_bounds__(256) void xquant_kernel(const float* __restrict__ x) {
    const int row = blockIdx.x;
    const int tid = threadIdx.x;
    const float4* xr = reinterpret_cast<const float4*>(x + (size_t)row * K_DIM);
    __shared__ float red[8];

    float m = 0.f;
    float4 v[4];
    #pragma unroll
    for (int i = 0; i < 4; i++) {
        v[i] = xr[tid + i * 256];
        m = fmaxf(m, fmaxf(fmaxf(fabsf(v[i].x), fabsf(v[i].y)),
                           fmaxf(fabsf(v[i].z), fabsf(v[i].w))));
    }
    #pragma unroll
    for (int o = 16; o > 0; o >>= 1)
        m = fmaxf(m, __shfl_xor_sync(0xffffffffu, m, o));
    if ((tid & 31) == 0) red[tid >> 5] = m;
    __syncthreads();
    if (tid < 8) {
        float t = red[tid];
        #pragma unroll
        for (int o = 4; o > 0; o >>= 1)
            t = fmaxf(t, __shfl_xor_sync(0xffu, t, o));
        if (tid == 0) red[0] = t;
    }
    __syncthreads();
    m = red[0];

    const float s1   = (m > 0.f) ? (m / 126.f) : 0.f;
    const float inv1 = (m > 0.f) ? (126.f / m) : 0.f;
    const float inv2 = inv1 * 254.f;

    int* oh = reinterpret_cast<int*>(g_xh8) + (size_t)row * (K_DIM / 4);
    int* ol = reinterpret_cast<int*>(g_xl8) + (size_t)row * (K_DIM / 4);
    #pragma unroll
    for (int i = 0; i < 4; i++) {
        float4 w = v[i];
        int h0 = __float2int_rn(w.x * inv1);
        int h1 = __float2int_rn(w.y * inv1);
        int h2 = __float2int_rn(w.z * inv1);
        int h3 = __float2int_rn(w.w * inv1);
        int l0 = __float2int_rn((w.x - (float)h0 * s1) * inv2);
        int l1 = __float2int_rn((w.y - (float)h1 * s1) * inv2);
        int l2 = __float2int_rn((w.z - (float)h2 * s1) * inv2);
        int l3 = __float2int_rn((w.w - (float)h3 * s1) * inv2);
        uint32_t ph = (uint32_t)(h0 & 0xff) | ((uint32_t)(h1 & 0xff) << 8) |
                      ((uint32_t)(h2 & 0xff) << 16) | ((uint32_t)(h3 & 0xff) << 24);
        uint32_t pl = (uint32_t)(l0 & 0xff) | ((uint32_t)(l1 & 0xff) << 8) |
                      ((uint32_t)(l2 & 0xff) << 16) | ((uint32_t)(l3 & 0xff) << 24);
        oh[tid + i * 256] = (int)ph;
        ol[tid + i * 256] = (int)pl;
    }
    if (tid == 0) g_s1[row] = s1;
}

// ---------------- GEMM kernel ----------------
// Per-stage smem: A_hi[128][64B] | A_lo[128][64B] | B[128][64B].
// Row = 64B = 4 chunks of 16B; physical chunk = c ^ ((row>>1)&3).
// Warp layout: 4 (m) x 2 (n); warp tile 32 x 64.
__global__ __launch_bounds__(THREADS, 1) void gemm_kernel(
    const float* __restrict__ scale_p,
    const float* __restrict__ bias,
    float* __restrict__ out) {
    extern __shared__ char smem[];
    uint32_t sb = smem_to_u32(smem);
    const int tid = threadIdx.x;
    const int lane = tid & 31, wid = tid >> 5;
    const int wm = wid >> 1;          // 0..3 -> 32-row slice
    const int wn = wid & 1;           // 0..1 -> 64-col slice

    const int m_tile = (int)blockIdx.x >> 5;   // 0..127
    const int n_tile = (int)blockIdx.x & 31;   // 0..31
    const int m0 = m_tile * BM;
    const int n0 = n_tile * BN;

    // cp.async assignment: 512 chunks of 16B per tile, 2 per thread, 3 tiles
    const int r1 = tid >> 2,          c1 = tid & 3;
    const int r2 = (tid + 256) >> 2,  c2 = (tid + 256) & 3;
    const uint32_t so1 = (uint32_t)(r1 * 64 + ((c1 ^ ((r1 >> 1) & 3)) << 4));
    const uint32_t so2 = (uint32_t)(r2 * 64 + ((c2 ^ ((r2 >> 1) & 3)) << 4));
    const int8_t* ghi1 = g_xh8 + (size_t)(m0 + r1) * K_DIM + c1 * 16;
    const int8_t* ghi2 = g_xh8 + (size_t)(m0 + r2) * K_DIM + c2 * 16;
    const int8_t* glo1 = g_xl8 + (size_t)(m0 + r1) * K_DIM + c1 * 16;
    const int8_t* glo2 = g_xl8 + (size_t)(m0 + r2) * K_DIM + c2 * 16;
    const int8_t* gb1  = g_wq  + (size_t)(n0 + r1) * K_DIM + c1 * 16;
    const int8_t* gb2  = g_wq  + (size_t)(n0 + r2) * K_DIM + c2 * 16;

    // ldmatrix per-lane address components.
    // All tile row-bases are multiples of 8 -> swizzle term sw=((lane&7)>>1)&3
    // is offset-invariant for both A and B.
    const int l7  = lane & 7;
    const int sw  = (l7 >> 1) & 3;
    const int b3  = (lane >> 3) & 1;
    const int b4  = (lane >> 4) & 1;
    // A (m16k32 frag via ldm_x4): rows l7 + 8*b3, chunk bit b4
    uint32_t rowbA[2];   // mi = 0,1
    #pragma unroll
    for (int mi = 0; mi < 2; mi++)
        rowbA[mi] = (uint32_t)((wm * 32 + mi * 16 + l7 + 8 * b3) * 64);
    // B (two n8k32 frags via ldm_x4): rows l7 + 8*b4, chunk bit b3
    uint32_t rowbB[4];   // p = 0..3 -> n-tiles 2p, 2p+1
    #pragma unroll
    for (int p = 0; p < 4; p++)
        rowbB[p] = (uint32_t)((wn * 64 + p * 16 + l7 + 8 * b4) * 64);
    uint32_t coA[2], coB[2];
    #pragma unroll
    for (int s = 0; s < 2; s++) {
        coA[s] = (uint32_t)((((s << 1) | b4) ^ sw) << 4);
        coB[s] = (uint32_t)((((s << 1) | b3) ^ sw) << 4);
    }

    // prologue: fill STAGES-1 = 5 stages
    #pragma unroll
    for (int kt = 0; kt < STAGES - 1; kt++) {
        uint32_t st = sb + kt * STAGE_BYTES;
        int ko = kt * BK;
        cp16(st + so1,           ghi1 + ko);
        cp16(st + so2,           ghi2 + ko);
        cp16(st + OFF_ALO + so1, glo1 + ko);
        cp16(st + OFF_ALO + so2, glo2 + ko);
        cp16(st + OFF_B + so1,   gb1 + ko);
        cp16(st + OFF_B + so2,   gb2 + ko);
        cp_commit();
    }

    int acch[2][8][4];
    int accl[2][8][4];
    #pragma unroll
    for (int i = 0; i < 2; i++)
        #pragma unroll
        for (int j = 0; j < 8; j++)
            #pragma unroll
            for (int l = 0; l < 4; l++) { acch[i][j][l] = 0; accl[i][j][l] = 0; }

    // fragment double buffers: [0] = step 0, [1] = step 1 of current k-tile
    uint32_t fb [2][4][4];
    uint32_t faH[2][2][4];
    uint32_t faL[2][2][4];

    auto load_frags = [&](int buf, uint32_t st, int s) {
        #pragma unroll
        for (int p = 0; p < 4; p++)
            ldm_x4(fb[buf][p], st + OFF_B + rowbB[p] + coB[s]);
        #pragma unroll
        for (int mi = 0; mi < 2; mi++)
            ldm_x4(faH[buf][mi], st + rowbA[mi] + coA[s]);
        #pragma unroll
        for (int mi = 0; mi < 2; mi++)
            ldm_x4(faL[buf][mi], st + OFF_ALO + rowbA[mi] + coA[s]);
    };

    auto do_mma = [&](int buf) {
        #pragma unroll
        for (int mi = 0; mi < 2; mi++)
            #pragma unroll
            for (int ni = 0; ni < 8; ni++) {
                const uint32_t* bp = &fb[buf][ni >> 1][(ni & 1) * 2];
                mma_s8(acch[mi][ni], faH[buf][mi], bp);
                mma_s8(accl[mi][ni], faL[buf][mi], bp);
            }
    };

    // pre-loop: stage 0 (and 1) ready; preload (kt=0, s=0) fragments
    asm volatile("cp.async.wait_group %0;" :: "n"(STAGES - 3) : "memory");
    __syncthreads();
    load_frags(0, sb, 0);

    uint32_t st  = sb;                                  // stage kt
    uint32_t stw = sb + (STAGES - 1) * STAGE_BYTES;     // stage (kt+5)%6

    for (int kt = 0; kt < NKT; kt++) {
        if (kt > 0) {
            asm volatile("cp.async.wait_group %0;" :: "n"(STAGES - 3) : "memory");
            __syncthreads();
        }
        int kn = kt + STAGES - 1;
        if (kn < NKT) {
            int ko = kn * BK;
            cp16(stw + so1,           ghi1 + ko);
            cp16(stw + so2,           ghi2 + ko);
            cp16(stw + OFF_ALO + so1, glo1 + ko);
            cp16(stw + OFF_ALO + so2, glo2 + ko);
            cp16(stw + OFF_B + so1,   gb1 + ko);
            cp16(stw + OFF_B + so2,   gb2 + ko);
        }
        cp_commit();

        // load step-1 fragments, then mma step 0 (frags from prev iteration)
        load_frags(1, st, 1);
        do_mma(0);

        // preload next tile's step-0 fragments (stage kt+1 data is ready
        // under wait_group(STAGES-3); its WAR refill is 2 barriers away)
        uint32_t stn = (st == sb + (STAGES - 1) * STAGE_BYTES) ? sb
                                                               : st + STAGE_BYTES;
        load_frags(0, stn, 0);   // at kt=NKT-1 reads stale data; results unused
        do_mma(1);

        st = stn;
        stw = (stw == sb + (STAGES - 1) * STAGE_BYTES) ? sb : stw + STAGE_BYTES;
    }

    // epilogue: out = sc*s1[m]*(hi + lo/254) + bias
    const float sc = __ldg(scale_p);
    #pragma unroll
    for (int mi = 0; mi < 2; mi++) {
        int r0 = m0 + wm * 32 + mi * 16 + (lane >> 2);
        float f0  = sc * __ldg(g_s1 + r0);
        float f1  = sc * __ldg(g_s1 + r0 + 8);
        float f0l = f0 * (1.f / 254.f);
        float f1l = f1 * (1.f / 254.f);
        float* o0 = out + (size_t)r0 * N_DIM;
        float* o1 = o0 + (size_t)8 * N_DIM;
        #pragma unroll
        for (int ni = 0; ni < 8; ni++) {
            int c = n0 + wn * 64 + ni * 8 + (lane & 3) * 2;
            float b0 = __ldg(bias + c), b1 = __ldg(bias + c + 1);
            float2 v0, v1;
            v0.x = f0 * (float)acch[mi][ni][0] + f0l * (float)accl[mi][ni][0] + b0;
            v0.y = f0 * (float)acch[mi][ni][1] + f0l * (float)accl[mi][ni][1] + b1;
            v1.x = f1 * (float)acch[mi][ni][2] + f1l * (float)accl[mi][ni][2] + b0;
            v1.y = f1 * (float)acch[mi][ni][3] + f1l * (float)accl[mi][ni][3] + b1;
            *reinterpret_cast<float2*>(o0 + c) = v0;
            *reinterpret_cast<float2*>(o1 + c) = v1;
        }
    }
}

// ---------------- host launch ----------------
extern "C" void kernel_launch(void* const* d_in, const int* in_sizes, int n_in,
                              void* d_out, int out_size) {
    const float* x     = (const float*)d_in[0];
    const int*   q     = (const int*)d_in[1];
    const float* scale = (const float*)d_in[2];
    const float* bias  = (const float*)d_in[3];
    float* out = (float*)d_out;

    wpack_kernel<<<1480, 256>>>(q);
    xquant_kernel<<<M_DIM, 256>>>(x);

    cudaFuncSetAttribute(gemm_kernel,
                         cudaFuncAttributeMaxDynamicSharedMemorySize, SMEM_TOTAL);
    dim3 grid((M_DIM / BM) * (N_DIM / BN));   // 4096
    gemm_kernel<<<grid, THREADS, SMEM_TOTAL>>>(scale, bias, out);
}